// round 2
// baseline (speedup 1.0000x reference)
#include <cuda_runtime.h>
#include <math_constants.h>

// Shapes
#define S_    1024
#define B_    256
#define N_    256
#define M_    512
#define E_    64
#define SM1   1023          // number of attention positions (S-1)
#define CHUNKS_PER_B 16     // 2 blocks * 8 warps
#define CHUNK_LEN    64

// Scratch (static device memory; no allocations allowed)
__device__ float g_zcp[8 * N_ * B_];          // D@z partials (k-split 8): [kc][b*256+n]
__device__ float g_zc [N_ * B_];              // zc[b*256+n] = (D@z)[n,b]
__device__ float g_pm [B_ * CHUNKS_PER_B];    // per-chunk running max
__device__ float g_pl [B_ * CHUNKS_PER_B];    // per-chunk sum
__device__ float g_pa [(size_t)B_ * CHUNKS_PER_B * 512]; // per-chunk A0(256)|A1(256)

// ---------------------------------------------------------------------------
// K0: zc partial GEMM.  zc[b][n] = sum_m D[n][m] * z[m][b]
// grid (16 n-tiles, 8 k-chunks), 256 threads (thread = b)
// ---------------------------------------------------------------------------
__global__ __launch_bounds__(256) void k0_zc(const float* __restrict__ D,
                                             const float* __restrict__ z) {
    __shared__ float sD[64][17]; // [m within chunk][n within tile], padded
    const int tid = threadIdx.x;
    const int nt = blockIdx.x;      // n-tile (16 n's)
    const int kc = blockIdx.y;      // k-chunk (64 m's)

    // cooperative load of D tile: D[(nt*16+nn)*512 + kc*64 + mm]
    #pragma unroll
    for (int e = 0; e < 4; e++) {
        int idx = tid + e * 256;          // 0..1023
        int nn = idx >> 6;
        int mm = idx & 63;
        sD[mm][nn] = __ldg(D + (size_t)(nt * 16 + nn) * 512 + kc * 64 + mm);
    }
    __syncthreads();

    float acc[16];
    #pragma unroll
    for (int i = 0; i < 16; i++) acc[i] = 0.f;

    const int b = tid;
    #pragma unroll 4
    for (int mm = 0; mm < 64; mm++) {
        float zv = __ldg(z + (size_t)(kc * 64 + mm) * B_ + b);
        #pragma unroll
        for (int nn = 0; nn < 16; nn++) acc[nn] += sD[mm][nn] * zv;
    }

    float* dst = g_zcp + (size_t)kc * (N_ * B_) + (size_t)b * 256 + nt * 16;
    #pragma unroll
    for (int w = 0; w < 4; w++) {
        float4 v = make_float4(acc[4*w], acc[4*w+1], acc[4*w+2], acc[4*w+3]);
        reinterpret_cast<float4*>(dst)[w] = v;
    }
}

// K0b: reduce the 8 k-chunks.  64 blocks x 256 threads, float4 granularity.
__global__ __launch_bounds__(256) void k0b_zc() {
    int i = blockIdx.x * 256 + threadIdx.x;  // float4 index, 16384 total
    float4 s = make_float4(0.f, 0.f, 0.f, 0.f);
    #pragma unroll
    for (int kc = 0; kc < 8; kc++) {
        float4 v = reinterpret_cast<const float4*>(g_zcp)[kc * 16384 + i];
        s.x += v.x; s.y += v.y; s.z += v.z; s.w += v.w;
    }
    reinterpret_cast<float4*>(g_zc)[i] = s;
}

// ---------------------------------------------------------------------------
// K1: main pass. One warp = one chunk of frames for one b.
// Online softmax over distances + weighted accumulation of rows (A0) and
// next rows (A1), all in registers (8 floats/lane each, N=256 per warp).
// grid (B, 2), 256 threads (8 warps).
// ---------------------------------------------------------------------------
__global__ __launch_bounds__(256) void k1_main(const float* __restrict__ ctx,
                                               const float* __restrict__ t1p) {
    const int b    = blockIdx.x;
    const int wid  = threadIdx.x >> 5;
    const int lane = threadIdx.x & 31;
    const int q    = blockIdx.y * 8 + wid;           // chunk id 0..15
    const int s0   = q * CHUNK_LEN;
    const int s1   = min(s0 + CHUNK_LEN, SM1);

    const float neg_invt = -1.0f / fmaxf(fabsf(__ldg(t1p)), 1e-4f);

    // z_cur for this b / lane's 8 n's
    const float4* zc4 = reinterpret_cast<const float4*>(g_zc + b * 256 + lane * 8);
    float4 za = zc4[0], zb = zc4[1];
    float zv[8] = {za.x, za.y, za.z, za.w, zb.x, zb.y, zb.z, zb.w};

    float c[8], a0[8], a1[8];
    #pragma unroll
    for (int j = 0; j < 8; j++) { a0[j] = 0.f; a1[j] = 0.f; }
    float m = -CUDART_INF_F, l = 0.f;

    const float* base = ctx + ((size_t)s0 * B_ + b) * N_ + lane * 8;
    {
        const float4* r4 = reinterpret_cast<const float4*>(base);
        float4 x = __ldg(r4), y = __ldg(r4 + 1);
        c[0]=x.x; c[1]=x.y; c[2]=x.z; c[3]=x.w;
        c[4]=y.x; c[5]=y.y; c[6]=y.z; c[7]=y.w;
    }

    for (int s = s0; s < s1; s++) {
        // prefetch row s+1 (<= 1023, valid)
        const float4* rn = reinterpret_cast<const float4*>(
            base + (size_t)(s - s0 + 1) * (B_ * N_));
        float4 x = __ldg(rn), y = __ldg(rn + 1);
        float cn[8] = {x.x, x.y, x.z, x.w, y.x, y.y, y.z, y.w};

        // L1 distance across N=256
        float d = 0.f;
        #pragma unroll
        for (int j = 0; j < 8; j++) d += fabsf(c[j] - zv[j]);
        #pragma unroll
        for (int off = 16; off; off >>= 1)
            d += __shfl_xor_sync(0xffffffffu, d, off);

        float v = d * neg_invt;   // logit
        float w;
        if (v > m) {              // warp-uniform branch
            float al = __expf(m - v);   // m=-inf -> 0 on first iter
            l = l * al + 1.f;
            #pragma unroll
            for (int j = 0; j < 8; j++) { a0[j] *= al; a1[j] *= al; }
            m = v; w = 1.f;
        } else {
            w = __expf(v - m);
            l += w;
        }
        #pragma unroll
        for (int j = 0; j < 8; j++) {
            a0[j] += w * c[j];
            a1[j] += w * cn[j];
            c[j] = cn[j];
        }
    }

    const int pidx = b * CHUNKS_PER_B + q;
    if (lane == 0) { g_pm[pidx] = m; g_pl[pidx] = l; }
    float* pa = g_pa + (size_t)pidx * 512 + lane * 8;
    reinterpret_cast<float4*>(pa)[0]       = make_float4(a0[0], a0[1], a0[2], a0[3]);
    reinterpret_cast<float4*>(pa)[1]       = make_float4(a0[4], a0[5], a0[6], a0[7]);
    reinterpret_cast<float4*>(pa + 256)[0] = make_float4(a1[0], a1[1], a1[2], a1[3]);
    reinterpret_cast<float4*>(pa + 256)[1] = make_float4(a1[4], a1[5], a1[6], a1[7]);
}

// ---------------------------------------------------------------------------
// K2: combine partials -> conv GEMM -> MLP -> softmax over E.
// 64 blocks, 4 b's per block, 256 threads.
// ---------------------------------------------------------------------------
#define BNB 4
__global__ __launch_bounds__(256) void k2_epilogue(
        const float* __restrict__ convw, const float* __restrict__ convb,
        const float* __restrict__ z,     const float* __restrict__ W1,
        const float* __restrict__ W2,    const float* __restrict__ t2p,
        float* __restrict__ out) {
    __shared__ float sA[BNB][512];       // normalized A, interleaved (a0,a1) per i
    __shared__ float sE[BNB][256];       // embeddings
    __shared__ float sScale[BNB][CHUNKS_PER_B];
    __shared__ float sL[BNB];
    __shared__ float sH[BNB][64];
    __shared__ float sRed[8], sRed2[8];

    const int tid = threadIdx.x;
    const int b0  = blockIdx.x * BNB;

    // step 1: per-b softmax stats over 16 chunk partials
    if (tid < BNB) {
        int b = b0 + tid;
        float M = -CUDART_INF_F;
        for (int q = 0; q < CHUNKS_PER_B; q++)
            M = fmaxf(M, g_pm[b * CHUNKS_PER_B + q]);
        float L = 0.f;
        for (int q = 0; q < CHUNKS_PER_B; q++) {
            float sc = __expf(g_pm[b * CHUNKS_PER_B + q] - M);
            sScale[tid][q] = sc;
            L += g_pl[b * CHUNKS_PER_B + q] * sc;
        }
        sL[tid] = L;
    }
    __syncthreads();

    // step 2: combine partial accumulators (thread = n)
    #pragma unroll
    for (int bb = 0; bb < BNB; bb++) {
        int b = b0 + bb;
        float a0 = 0.f, a1 = 0.f;
        #pragma unroll
        for (int q = 0; q < CHUNKS_PER_B; q++) {
            float sc = sScale[bb][q];
            const float* p = g_pa + (size_t)(b * CHUNKS_PER_B + q) * 512;
            a0 += p[tid] * sc;
            a1 += p[256 + tid] * sc;
        }
        float invL = 1.0f / sL[bb];
        sA[bb][2 * tid]     = a0 * invL;
        sA[bb][2 * tid + 1] = a1 * invL;
    }
    __syncthreads();

    // step 3: conv GEMM: emb[bb][o] = conv_b[o] + sum_j sA[bb][j]*conv_w[o][j]
    {
        const int o = tid;
        float cb = __ldg(convb + o);
        float acc[BNB];
        #pragma unroll
        for (int bb = 0; bb < BNB; bb++) acc[bb] = cb;
        const float4* w4 = reinterpret_cast<const float4*>(convw + (size_t)o * 512);
        #pragma unroll 4
        for (int jj = 0; jj < 128; jj++) {
            float4 wv = __ldg(w4 + jj);
            #pragma unroll
            for (int bb = 0; bb < BNB; bb++) {
                float4 av = reinterpret_cast<const float4*>(sA[bb])[jj];
                acc[bb] += wv.x * av.x + wv.y * av.y + wv.z * av.z + wv.w * av.w;
            }
        }
        #pragma unroll
        for (int bb = 0; bb < BNB; bb++) sE[bb][o] = acc[bb];
    }
    __syncthreads();

    // step 4: MLP layer 1 (+ReLU). thread = (bb, e)
    {
        const int bb = tid >> 6, e = tid & 63, b = b0 + bb;
        const float* w1r = W1 + (size_t)e * 768;
        float h = 0.f;
        #pragma unroll 4
        for (int j = 0; j < 256; j++) h += sE[bb][j] * __ldg(w1r + j);
        #pragma unroll 4
        for (int mm = 0; mm < 512; mm++)
            h += __ldg(z + (size_t)mm * B_ + b) * __ldg(w1r + 256 + mm);
        sH[bb][e] = fmaxf(h, 0.f);
    }
    __syncthreads();

    // step 5: layer 2 + softmax over E=64 (group of 2 warps per bb)
    {
        const int bb = tid >> 6, e = tid & 63, b = b0 + bb;
        const int wd = tid >> 5, lane = tid & 31;
        const float* w2r = W2 + e * 64;
        float acc = 0.f;
        #pragma unroll
        for (int e2 = 0; e2 < 64; e2++) acc += sH[bb][e2] * __ldg(w2r + e2);
        float t2 = fmaxf(fabsf(__ldg(t2p)), 1e-4f);
        float v = -acc / t2;

        float mx = v;
        #pragma unroll
        for (int off = 16; off; off >>= 1)
            mx = fmaxf(mx, __shfl_xor_sync(0xffffffffu, mx, off));
        if (lane == 0) sRed[wd] = mx;
        __syncthreads();
        mx = fmaxf(sRed[wd], sRed[wd ^ 1]);
        float ev = __expf(v - mx);
        float sm = ev;
        #pragma unroll
        for (int off = 16; off; off >>= 1)
            sm += __shfl_xor_sync(0xffffffffu, sm, off);
        if (lane == 0) sRed2[wd] = sm;
        __syncthreads();
        sm = sRed2[wd] + sRed2[wd ^ 1];
        out[(size_t)e * B_ + b] = ev / sm;
    }
}

// ---------------------------------------------------------------------------
extern "C" void kernel_launch(void* const* d_in, const int* in_sizes, int n_in,
                              void* d_out, int out_size) {
    const float* ctx   = (const float*)d_in[0];
    const float* z     = (const float*)d_in[1];
    const float* D     = (const float*)d_in[2];
    const float* convw = (const float*)d_in[3];
    const float* convb = (const float*)d_in[4];
    const float* W1    = (const float*)d_in[5];
    const float* W2    = (const float*)d_in[6];
    const float* t1    = (const float*)d_in[7];
    const float* t2    = (const float*)d_in[8];
    float* out = (float*)d_out;

    k0_zc<<<dim3(16, 8), 256>>>(D, z);
    k0b_zc<<<64, 256>>>();
    k1_main<<<dim3(B_, 2), 256>>>(ctx, t1);
    k2_epilogue<<<64, 256>>>(convw, convb, z, W1, W2, t2, out);
}

// round 4
// speedup vs baseline: 1.9408x; 1.9408x over previous
#include <cuda_runtime.h>
#include <math_constants.h>

// Shapes
#define S_    1024
#define B_    256
#define N_    256
#define M_    512
#define E_    64
#define SM1   1023
#define CHUNKS_PER_B 16
#define CHUNK_LEN    64

// Scratch (static device memory)
__device__ float g_zcp [8 * N_ * B_];                    // zc split-k partials [kc][b*256+n]
__device__ float g_cwT [M_ * N_];                        // conv_w transposed: [j(512)][o(256)]
__device__ float g_w1zp[8 * E_ * B_];                    // W1z split-k partials [(mc*64+e)*256+b]
__device__ float g_pm  [B_ * CHUNKS_PER_B];
__device__ float g_pl  [B_ * CHUNKS_PER_B];
__device__ float g_pa  [(size_t)B_ * CHUNKS_PER_B * 512];

// ---------------------------------------------------------------------------
// P1: fused prologue. 288 blocks, 256 threads.
//   blocks [0,128):   zc split-k partials  (nt = id&15 -> 16 n's, kc = id>>4 -> 64 m's)
//   blocks [128,256): conv_w transpose, 32x32 tiles
//   blocks [256,288): W1z split-k partials (et = w&3 -> 16 e's, mc = w>>2 -> 64 m's)
// ---------------------------------------------------------------------------
__global__ __launch_bounds__(256) void p1_prologue(const float* __restrict__ D,
                                                   const float* __restrict__ z,
                                                   const float* __restrict__ convw,
                                                   const float* __restrict__ W1) {
    __shared__ float sbuf[64 * 17];   // union: k0 [64][17] / kT [32][33] / W1z [16][64]
    const int tid = threadIdx.x;
    const int bid = blockIdx.x;

    if (bid < 128) {
        // ---- zc partials: zcp[kc][b][n16] = sum_{m in chunk} D[n][m] z[m][b]
        float (*sD)[17] = reinterpret_cast<float (*)[17]>(sbuf);
        const int nt = bid & 15, kc = bid >> 4;
        #pragma unroll
        for (int e = 0; e < 4; e++) {
            int idx = tid + e * 256;
            int nn = idx >> 6, mm = idx & 63;
            sD[mm][nn] = __ldg(D + (size_t)(nt * 16 + nn) * 512 + kc * 64 + mm);
        }
        __syncthreads();
        float acc[16];
        #pragma unroll
        for (int i = 0; i < 16; i++) acc[i] = 0.f;
        const int b = tid;
        #pragma unroll 4
        for (int mm = 0; mm < 64; mm++) {
            float zv = __ldg(z + (size_t)(kc * 64 + mm) * B_ + b);
            #pragma unroll
            for (int nn = 0; nn < 16; nn++) acc[nn] += sD[mm][nn] * zv;
        }
        float* dst = g_zcp + (size_t)kc * (N_ * B_) + (size_t)b * 256 + nt * 16;
        #pragma unroll
        for (int w = 0; w < 4; w++)
            reinterpret_cast<float4*>(dst)[w] =
                make_float4(acc[4*w], acc[4*w+1], acc[4*w+2], acc[4*w+3]);
    } else if (bid < 256) {
        // ---- transpose conv_w [o(256)][j(512)] -> g_cwT [j][o], 32x32 tile
        float (*st)[33] = reinterpret_cast<float (*)[33]>(sbuf);
        const int t = bid - 128;
        const int j0 = (t & 15) * 32, o0 = (t >> 4) * 32;
        const int tx = tid & 31, ty = tid >> 5;   // ty 0..7
        #pragma unroll
        for (int k = 0; k < 4; k++) {
            int row = ty + k * 8;
            st[row][tx] = __ldg(convw + (size_t)(o0 + row) * 512 + j0 + tx);
        }
        __syncthreads();
        #pragma unroll
        for (int k = 0; k < 4; k++) {
            int row = ty + k * 8;
            g_cwT[(size_t)(j0 + row) * 256 + o0 + tx] = st[tx][row];
        }
    } else {
        // ---- W1z partials: w1zp[mc][e][b] = sum_{m in chunk} W1[e][256+m] z[m][b]
        float (*sW)[64] = reinterpret_cast<float (*)[64]>(sbuf);
        const int w = bid - 256;
        const int et = w & 3, mc = w >> 2;
        {
            int idx = tid * 4;                  // 1024 elements, 4 per thread
            int e_l = idx >> 6, mm = idx & 63;
            float4 v = __ldg(reinterpret_cast<const float4*>(
                W1 + (size_t)(et * 16 + e_l) * 768 + 256 + mc * 64 + mm));
            sW[e_l][mm] = v.x; sW[e_l][mm+1] = v.y; sW[e_l][mm+2] = v.z; sW[e_l][mm+3] = v.w;
        }
        __syncthreads();
        float acc[16];
        #pragma unroll
        for (int i = 0; i < 16; i++) acc[i] = 0.f;
        const int b = tid;
        #pragma unroll 4
        for (int mm = 0; mm < 64; mm++) {
            float zv = __ldg(z + (size_t)(mc * 64 + mm) * B_ + b);
            #pragma unroll
            for (int e = 0; e < 16; e++) acc[e] += sW[e][mm] * zv;
        }
        #pragma unroll
        for (int e = 0; e < 16; e++)
            g_w1zp[(size_t)(mc * 64 + et * 16 + e) * 256 + b] = acc[e];
    }
}

// ---------------------------------------------------------------------------
// K1: main context pass (zc k-reduction folded into the head).
// grid (256, 2), 256 threads (8 warps, warp = 64-frame chunk).
// ---------------------------------------------------------------------------
__global__ __launch_bounds__(256) void k1_main(const float* __restrict__ ctx,
                                               const float* __restrict__ t1p) {
    const int b    = blockIdx.x;
    const int wid  = threadIdx.x >> 5;
    const int lane = threadIdx.x & 31;
    const int q    = blockIdx.y * 8 + wid;
    const int s0   = q * CHUNK_LEN;
    const int s1   = min(s0 + CHUNK_LEN, SM1);

    const float neg_invt = -1.0f / fmaxf(fabsf(__ldg(t1p)), 1e-4f);

    // zc[b][lane*8..+8] = sum of 8 split-k partials
    float zv[8];
    #pragma unroll
    for (int j = 0; j < 8; j++) zv[j] = 0.f;
    #pragma unroll
    for (int kc = 0; kc < 8; kc++) {
        const float4* p = reinterpret_cast<const float4*>(
            g_zcp + (size_t)kc * (N_ * B_) + (size_t)b * 256 + lane * 8);
        float4 x = p[0], y = p[1];
        zv[0] += x.x; zv[1] += x.y; zv[2] += x.z; zv[3] += x.w;
        zv[4] += y.x; zv[5] += y.y; zv[6] += y.z; zv[7] += y.w;
    }

    float c[8], a0[8], a1[8];
    #pragma unroll
    for (int j = 0; j < 8; j++) { a0[j] = 0.f; a1[j] = 0.f; }
    float m = -CUDART_INF_F, l = 0.f;

    const float* base = ctx + ((size_t)s0 * B_ + b) * N_ + lane * 8;
    {
        const float4* r4 = reinterpret_cast<const float4*>(base);
        float4 x = __ldg(r4), y = __ldg(r4 + 1);
        c[0]=x.x; c[1]=x.y; c[2]=x.z; c[3]=x.w;
        c[4]=y.x; c[5]=y.y; c[6]=y.z; c[7]=y.w;
    }

    for (int s = s0; s < s1; s++) {
        const float4* rn = reinterpret_cast<const float4*>(
            base + (size_t)(s - s0 + 1) * (B_ * N_));
        float4 x = __ldg(rn), y = __ldg(rn + 1);
        float cn[8] = {x.x, x.y, x.z, x.w, y.x, y.y, y.z, y.w};

        float d = 0.f;
        #pragma unroll
        for (int j = 0; j < 8; j++) d += fabsf(c[j] - zv[j]);
        #pragma unroll
        for (int off = 16; off; off >>= 1)
            d += __shfl_xor_sync(0xffffffffu, d, off);

        float v = d * neg_invt;
        float w;
        if (v > m) {
            float al = __expf(m - v);
            l = l * al + 1.f;
            #pragma unroll
            for (int j = 0; j < 8; j++) { a0[j] *= al; a1[j] *= al; }
            m = v; w = 1.f;
        } else {
            w = __expf(v - m);
            l += w;
        }
        #pragma unroll
        for (int j = 0; j < 8; j++) {
            a0[j] += w * c[j];
            a1[j] += w * cn[j];
            c[j] = cn[j];
        }
    }

    const int pidx = b * CHUNKS_PER_B + q;
    if (lane == 0) { g_pm[pidx] = m; g_pl[pidx] = l; }
    float* pa = g_pa + (size_t)pidx * 512 + lane * 8;
    reinterpret_cast<float4*>(pa)[0]       = make_float4(a0[0], a0[1], a0[2], a0[3]);
    reinterpret_cast<float4*>(pa)[1]       = make_float4(a0[4], a0[5], a0[6], a0[7]);
    reinterpret_cast<float4*>(pa + 256)[0] = make_float4(a1[0], a1[1], a1[2], a1[3]);
    reinterpret_cast<float4*>(pa + 256)[1] = make_float4(a1[4], a1[5], a1[6], a1[7]);
}

// ---------------------------------------------------------------------------
// K2: combine -> conv GEMM (coalesced via g_cwT) -> MLP -> softmax.
// 64 blocks x 4 b, 256 threads.
// ---------------------------------------------------------------------------
#define BNB 4
__global__ __launch_bounds__(256) void k2_epilogue(
        const float* __restrict__ convb, const float* __restrict__ W1,
        const float* __restrict__ W2,    const float* __restrict__ t2p,
        float* __restrict__ out) {
    __shared__ float sA[BNB][512];
    __shared__ float sE[BNB][260];
    __shared__ float sScale[BNB][CHUNKS_PER_B];
    __shared__ float sL[BNB];
    __shared__ float sW1[64][33];
    __shared__ float sW2[64][65];
    __shared__ float sH[BNB][64];
    __shared__ float sRed[8], sRed2[8];

    const int tid = threadIdx.x;
    const int b0  = blockIdx.x * BNB;

    // step 1: per-b softmax merge stats
    if (tid < BNB) {
        int b = b0 + tid;
        float M = -CUDART_INF_F;
        #pragma unroll
        for (int q = 0; q < CHUNKS_PER_B; q++)
            M = fmaxf(M, g_pm[b * CHUNKS_PER_B + q]);
        float L = 0.f;
        #pragma unroll
        for (int q = 0; q < CHUNKS_PER_B; q++) {
            float sc = __expf(g_pm[b * CHUNKS_PER_B + q] - M);
            sScale[tid][q] = sc;
            L += g_pl[b * CHUNKS_PER_B + q] * sc;
        }
        sL[tid] = L;
    }
    // stage W2 while stats run (coalesced, 16 floats/thread)
    {
        int e_l = tid >> 2, off = (tid & 3) * 16;
        #pragma unroll
        for (int k = 0; k < 4; k++) {
            float4 v = __ldg(reinterpret_cast<const float4*>(W2 + e_l * 64 + off + k * 4));
            sW2[e_l][off + k*4] = v.x; sW2[e_l][off + k*4+1] = v.y;
            sW2[e_l][off + k*4+2] = v.z; sW2[e_l][off + k*4+3] = v.w;
        }
    }
    __syncthreads();

    // step 2: combine partial accumulators (thread = n, coalesced)
    #pragma unroll
    for (int bb = 0; bb < BNB; bb++) {
        int b = b0 + bb;
        float a0 = 0.f, a1 = 0.f;
        #pragma unroll
        for (int q = 0; q < CHUNKS_PER_B; q++) {
            float sc = sScale[bb][q];
            const float* p = g_pa + (size_t)(b * CHUNKS_PER_B + q) * 512;
            a0 += p[tid] * sc;
            a1 += p[256 + tid] * sc;
        }
        float invL = 1.0f / sL[bb];
        sA[bb][2 * tid]     = a0 * invL;
        sA[bb][2 * tid + 1] = a1 * invL;
    }
    __syncthreads();

    // step 3: conv GEMM, coalesced: emb[bb][o] = convb[o] + sum_j cwT[j][o]*sA[bb][j]
    {
        const int o = tid;
        float cb = __ldg(convb + o);
        float acc[BNB];
        #pragma unroll
        for (int bb = 0; bb < BNB; bb++) acc[bb] = cb;
        #pragma unroll 8
        for (int j = 0; j < 512; j++) {
            float w = g_cwT[(size_t)j * 256 + o];     // coalesced, L2-resident
            #pragma unroll
            for (int bb = 0; bb < BNB; bb++) acc[bb] += w * sA[bb][j];
        }
        #pragma unroll
        for (int bb = 0; bb < BNB; bb++) sE[bb][o] = acc[bb];
    }
    __syncthreads();

    // step 4: MLP layer 1 (+ReLU). thread = (bb, e); z-half precomputed in g_w1zp
    {
        const int bb = tid >> 6, e = tid & 63, b = b0 + bb;
        float h = 0.f;
        #pragma unroll
        for (int mc = 0; mc < 8; mc++)
            h += g_w1zp[(size_t)(mc * 64 + e) * 256 + b];
        #pragma unroll 1
        for (int jc = 0; jc < 8; jc++) {          // 32-wide k chunks of the emb half
            {   // stage W1[e][jc*32 .. +32] for all 64 e (coalesced float4)
                int e_l = tid >> 2, part = (tid & 3) * 8;
                float4 v0 = __ldg(reinterpret_cast<const float4*>(
                    W1 + (size_t)e_l * 768 + jc * 32 + part));
                float4 v1 = __ldg(reinterpret_cast<const float4*>(
                    W1 + (size_t)e_l * 768 + jc * 32 + part + 4));
                sW1[e_l][part]   = v0.x; sW1[e_l][part+1] = v0.y;
                sW1[e_l][part+2] = v0.z; sW1[e_l][part+3] = v0.w;
                sW1[e_l][part+4] = v1.x; sW1[e_l][part+5] = v1.y;
                sW1[e_l][part+6] = v1.z; sW1[e_l][part+7] = v1.w;
            }
            __syncthreads();
            #pragma unroll
            for (int jj = 0; jj < 32; jj++)
                h += sW1[e][jj] * sE[bb][jc * 32 + jj];
            __syncthreads();
        }
        sH[bb][e] = fmaxf(h, 0.f);
    }
    __syncthreads();

    // step 5: layer 2 + softmax over E=64
    {
        const int bb = tid >> 6, e = tid & 63, b = b0 + bb;
        const int wd = tid >> 5, lane = tid & 31;
        float acc = 0.f;
        #pragma unroll
        for (int e2 = 0; e2 < 64; e2++) acc += sH[bb][e2] * sW2[e][e2];
        float t2 = fmaxf(fabsf(__ldg(t2p)), 1e-4f);
        float v = -acc / t2;

        float mx = v;
        #pragma unroll
        for (int off = 16; off; off >>= 1)
            mx = fmaxf(mx, __shfl_xor_sync(0xffffffffu, mx, off));
        if (lane == 0) sRed[wd] = mx;
        __syncthreads();
        mx = fmaxf(sRed[wd], sRed[wd ^ 1]);
        float ev = __expf(v - mx);
        float sm = ev;
        #pragma unroll
        for (int off = 16; off; off >>= 1)
            sm += __shfl_xor_sync(0xffffffffu, sm, off);
        if (lane == 0) sRed2[wd] = sm;
        __syncthreads();
        sm = sRed2[wd] + sRed2[wd ^ 1];
        out[(size_t)e * B_ + b] = ev / sm;
    }
}

// ---------------------------------------------------------------------------
extern "C" void kernel_launch(void* const* d_in, const int* in_sizes, int n_in,
                              void* d_out, int out_size) {
    const float* ctx   = (const float*)d_in[0];
    const float* z     = (const float*)d_in[1];
    const float* D     = (const float*)d_in[2];
    const float* convw = (const float*)d_in[3];
    const float* convb = (const float*)d_in[4];
    const float* W1    = (const float*)d_in[5];
    const float* W2    = (const float*)d_in[6];
    const float* t1    = (const float*)d_in[7];
    const float* t2    = (const float*)d_in[8];
    float* out = (float*)d_out;

    p1_prologue<<<288, 256>>>(D, z, convw, W1);
    k1_main<<<dim3(B_, 2), 256>>>(ctx, t1);
    k2_epilogue<<<64, 256>>>(convb, W1, W2, t2, out);
}